// round 16
// baseline (speedup 1.0000x reference)
#include <cuda_runtime.h>
#include <math.h>

#define T_STEPS 2048
#define D_IN    16
#define H_DIM   256
#define N_APP   10
#define DT_VAL  0.1f
#define LN_EPS  1e-5f

// Shared memory layout (floats):
//  WSM [3][32][260] = 24960  W_rec rows i=128+4l+rr+1 (rr=0..2), conflict-free pad 260
//  WIN [256][20]    = 5120
//  PRM [6][256]     = 1536   (b_in, g_intra, b_intra, decay, g_norm, b_norm)
//  H   [256], REC [256], USM [2][256], XS [2][16], RED [16]
#define SM_WSM 0
#define SM_WIN (SM_WSM + 24960)
#define SM_PRM (SM_WIN + 5120)
#define SM_H   (SM_PRM + 1536)
#define SM_REC (SM_H + 256)
#define SM_USM (SM_REC + 256)
#define SM_XS  (SM_USM + 512)
#define SM_RED (SM_XS + 32)
#define SM_TOT (SM_RED + 16)
#define SM_BYTES (SM_TOT * 4)

typedef unsigned long long ull;

__device__ __forceinline__ ull fma2(ull a, ull b, ull c) {
    ull d;
    asm("fma.rn.f32x2 %0, %1, %2, %3;" : "=l"(d) : "l"(a), "l"(b), "l"(c));
    return d;
}
__device__ __forceinline__ ull dupf2(float v) {
    ull d;
    asm("mov.b64 %0, {%1, %1};" : "=l"(d) : "f"(v));
    return d;
}
__device__ __forceinline__ float lo32(ull a) { return __uint_as_float((unsigned)a); }
__device__ __forceinline__ float hi32(ull a) { return __uint_as_float((unsigned)(a >> 32)); }

extern "C" __global__ void __launch_bounds__(512, 1)
liquid_net_kernel(const float* __restrict__ x,
                  const float* __restrict__ W_in,
                  const float* __restrict__ b_in,
                  const float* __restrict__ tau_param,
                  const float* __restrict__ W_rec,
                  const float* __restrict__ g_intra,
                  const float* __restrict__ b_intra,
                  const float* __restrict__ g_norm,
                  const float* __restrict__ b_norm,
                  const float* __restrict__ W_head,
                  const float* __restrict__ b_head,
                  float* __restrict__ out)
{
    extern __shared__ float sm[];
    float* Wsm  = sm + SM_WSM;
    float* Win  = sm + SM_WIN;
    float* prm  = sm + SM_PRM;
    float* h_sh = sm + SM_H;
    float* rec  = sm + SM_REC;
    float* usm  = sm + SM_USM;
    float* xs   = sm + SM_XS;
    float* red  = sm + SM_RED;

    const int t = threadIdx.x;
    const int b = blockIdx.x;
    const int w = t >> 5;     // warp: owns j-block [16w, 16w+16)
    const int l = t & 31;     // lane: owns i in {4l..4l+3, 128+4l..128+4l+3}

    // ---------------- init ----------------
    // smem W rows: i = 128 + 4*lane + rr + 1, rr in [0,3)
    for (int idx = t; idx < 3 * 32 * 256; idx += 512) {
        int j   = idx & 255;
        int row = idx >> 8;          // 0..95
        int rr  = row >> 5;
        int ll  = row & 31;
        Wsm[row * 260 + j] = W_rec[(128 + 4 * ll + rr + 1) * 256 + j];
    }
    for (int idx = t; idx < 4096; idx += 512) {
        int jj = idx >> 4;
        int i  = idx & 15;
        Win[jj * 20 + i] = W_in[jj * 16 + i];
    }
    if (t < 256) {
        prm[t]        = b_in[t];
        prm[256 + t]  = g_intra[t];
        prm[512 + t]  = b_intra[t];
        float tau = log1pf(expf(tau_param[t]));
        prm[768 + t]  = 1.0f - DT_VAL / tau;
        prm[1024 + t] = g_norm[t];
        prm[1280 + t] = b_norm[t];
        h_sh[t] = 0.0f;
    }
    if (t < 32) {
        // xs[0] = x_0, xs[1] = x_1
        int buf = t >> 4, i = t & 15;
        xs[buf * 16 + i] = x[((size_t)b * T_STEPS + buf) * D_IN + i];
    }

    // Register W rows: i = 4l+rr (rr=0..3) and i = 128+4l. Packed over j pairs.
    ull wr0[8], wr1[8], wr2[8], wr3[8], wh0[8];
    {
        const int jb = 16 * w;
        const float2* p0 = (const float2*)(W_rec + (size_t)(4 * l + 0) * 256 + jb);
        const float2* p1 = (const float2*)(W_rec + (size_t)(4 * l + 1) * 256 + jb);
        const float2* p2 = (const float2*)(W_rec + (size_t)(4 * l + 2) * 256 + jb);
        const float2* p3 = (const float2*)(W_rec + (size_t)(4 * l + 3) * 256 + jb);
        const float2* ph = (const float2*)(W_rec + (size_t)(128 + 4 * l) * 256 + jb);
        #pragma unroll
        for (int p = 0; p < 8; p++) {
            float2 a;
            a = p0[p]; wr0[p] = (ull)__float_as_uint(a.x) | ((ull)__float_as_uint(a.y) << 32);
            a = p1[p]; wr1[p] = (ull)__float_as_uint(a.x) | ((ull)__float_as_uint(a.y) << 32);
            a = p2[p]; wr2[p] = (ull)__float_as_uint(a.x) | ((ull)__float_as_uint(a.y) << 32);
            a = p3[p]; wr3[p] = (ull)__float_as_uint(a.x) | ((ull)__float_as_uint(a.y) << 32);
            a = ph[p]; wh0[p] = (ull)__float_as_uint(a.x) | ((ull)__float_as_uint(a.y) << 32);
        }
    }
    __syncthreads();

    // prologue: warps 8-15 compute u_0 into usm[0]
    if (t >= 256) {
        int j = t - 256;
        float u = prm[j];
        const float* wi = Win + j * 20;
        #pragma unroll
        for (int i = 0; i < 16; i++) u = fmaf(xs[i], wi[i], u);
        usm[j] = u;
    }
    __syncthreads();

    const float* wsm_base = Wsm + l * 260 + 16 * w;
    const int j_ln = t & 255;   // for LN threads (t<256) this is j

    // bit-reversed lane nibble -> j offset this lane's reduced value maps to
    const int m = ((l & 1) << 3) | ((l & 2) << 1) | ((l & 4) >> 1) | ((l & 8) >> 3);

    // ---------------- recurrence ----------------
    for (int step = 0; step < T_STEPS; ++step) {
        // ---- GEMV: all 16 warps ----
        float4 hlo = *(const float4*)(h_sh + 4 * l);
        float4 hhi = *(const float4*)(h_sh + 128 + 4 * l);

        ull acc[8];
        {
            ull hp = dupf2(hlo.x);
            #pragma unroll
            for (int p = 0; p < 8; p++) acc[p] = fma2(hp, wr0[p], 0ull);
        }
        {
            ull hp = dupf2(hlo.y);
            #pragma unroll
            for (int p = 0; p < 8; p++) acc[p] = fma2(hp, wr1[p], acc[p]);
        }
        {
            ull hp = dupf2(hlo.z);
            #pragma unroll
            for (int p = 0; p < 8; p++) acc[p] = fma2(hp, wr2[p], acc[p]);
        }
        {
            ull hp = dupf2(hlo.w);
            #pragma unroll
            for (int p = 0; p < 8; p++) acc[p] = fma2(hp, wr3[p], acc[p]);
        }
        {
            ull hp = dupf2(hhi.x);
            #pragma unroll
            for (int p = 0; p < 8; p++) acc[p] = fma2(hp, wh0[p], acc[p]);
        }
        // 3 smem rows: i = 128+4l+1(+2,+3) -> hhi.y,.z,.w
        {
            float hv[3] = { hhi.y, hhi.z, hhi.w };
            #pragma unroll
            for (int rr = 0; rr < 3; rr++) {
                const ulonglong2* wp = (const ulonglong2*)(wsm_base + rr * (32 * 260));
                ull hp = dupf2(hv[rr]);
                #pragma unroll
                for (int c = 0; c < 4; c++) {
                    ulonglong2 wv = wp[c];
                    acc[2 * c]     = fma2(hp, wv.x, acc[2 * c]);
                    acc[2 * c + 1] = fma2(hp, wv.y, acc[2 * c + 1]);
                }
            }
        }

        // ---- intra-warp reduce: 16 j-values across 32 lanes ----
        float v[16];
        #pragma unroll
        for (int p = 0; p < 8; p++) { v[2 * p] = lo32(acc[p]); v[2 * p + 1] = hi32(acc[p]); }
        {   // off=1, keep-half = 8
            bool up = (l & 1);
            #pragma unroll
            for (int k = 0; k < 8; k++) {
                float send = up ? v[k] : v[8 + k];
                float keep = up ? v[8 + k] : v[k];
                v[k] = keep + __shfl_xor_sync(0xffffffffu, send, 1);
            }
        }
        {   // off=2, half=4
            bool up = (l & 2);
            #pragma unroll
            for (int k = 0; k < 4; k++) {
                float send = up ? v[k] : v[4 + k];
                float keep = up ? v[4 + k] : v[k];
                v[k] = keep + __shfl_xor_sync(0xffffffffu, send, 2);
            }
        }
        {   // off=4, half=2
            bool up = (l & 4);
            #pragma unroll
            for (int k = 0; k < 2; k++) {
                float send = up ? v[k] : v[2 + k];
                float keep = up ? v[2 + k] : v[k];
                v[k] = keep + __shfl_xor_sync(0xffffffffu, send, 4);
            }
        }
        {   // off=8, half=1
            bool up = (l & 8);
            float send = up ? v[0] : v[1];
            float keep = up ? v[1] : v[0];
            v[0] = keep + __shfl_xor_sync(0xffffffffu, send, 8);
        }
        v[0] += __shfl_xor_sync(0xffffffffu, v[0], 16);
        if (l < 16) rec[16 * w + m] = v[0];

        // ---- asymmetric mid-step barrier: producers arrive (non-blocking),
        //      consumers sync. Warps 8-15 flow straight into proj work. ----
        if (t < 256) {
            asm volatile("bar.sync 2, 512;" ::: "memory");

            // ---- LN + state update (warps 0-7) ----
            float pre = rec[j_ln] + usm[(step & 1) * 256 + j_ln];

            float s  = pre;
            float s2 = pre * pre;
            #pragma unroll
            for (int off = 16; off > 0; off >>= 1) {
                s  += __shfl_xor_sync(0xffffffffu, s,  off);
                s2 += __shfl_xor_sync(0xffffffffu, s2, off);
            }
            if (l == 0) { red[w] = s; red[8 + w] = s2; }
            asm volatile("bar.sync 1, 256;" ::: "memory");
            float sum = 0.0f, sum2 = 0.0f;
            #pragma unroll
            for (int k = 0; k < 8; k++) { sum += red[k]; sum2 += red[8 + k]; }
            float mu   = sum * (1.0f / H_DIM);
            float var  = fmaf(-mu, mu, sum2 * (1.0f / H_DIM));
            float rstd = rsqrtf(var + LN_EPS);

            float f = tanhf(fmaf((pre - mu) * rstd, prm[256 + j_ln], prm[512 + j_ln]));
            float hn = fmaf(h_sh[j_ln], prm[768 + j_ln], DT_VAL * f);
            hn = fminf(10.0f, fmaxf(-10.0f, hn));
            h_sh[j_ln] = hn;
        } else {
            asm volatile("bar.arrive 2, 512;" ::: "memory");

            // ---- warps 8-15: next-step input projection + x prefetch ----
            int j = t - 256;
            int ns = step + 1;
            const float* xq = xs + (ns & 1) * 16;
            float u = prm[j];
            const float* wi = Win + j * 20;
            #pragma unroll
            for (int i = 0; i < 16; i++) u = fmaf(xq[i], wi[i], u);
            usm[(ns & 1) * 256 + j] = u;

            if (j < 16) {
                int ps = step + 2;
                int cl = ps < T_STEPS ? ps : (T_STEPS - 1);
                float xv = x[((size_t)b * T_STEPS + cl) * D_IN + j];
                xs[(ps & 1) * 16 + j] = xv;
            }
        }
        __syncthreads();
    }

    // ---------------- final LN + head ----------------
    if (t < 256) {
        float hv = h_sh[j_ln];
        float s  = hv;
        float s2 = hv * hv;
        #pragma unroll
        for (int off = 16; off > 0; off >>= 1) {
            s  += __shfl_xor_sync(0xffffffffu, s,  off);
            s2 += __shfl_xor_sync(0xffffffffu, s2, off);
        }
        int w8 = t >> 5;
        if ((t & 31) == 0) { red[w8] = s; red[8 + w8] = s2; }
        asm volatile("bar.sync 1, 256;" ::: "memory");
        float sum = 0.0f, sum2 = 0.0f;
        #pragma unroll
        for (int k = 0; k < 8; k++) { sum += red[k]; sum2 += red[8 + k]; }
        float mu   = sum * (1.0f / H_DIM);
        float var  = fmaf(-mu, mu, sum2 * (1.0f / H_DIM));
        float rstd = rsqrtf(var + LN_EPS);
        float hn = fmaf((hv - mu) * rstd, prm[1024 + j_ln], prm[1280 + j_ln]);
        rec[j_ln] = hn;
        asm volatile("bar.sync 1, 256;" ::: "memory");

        if (t < N_APP) {
            float o = b_head[t];
            #pragma unroll 8
            for (int k = 0; k < H_DIM; k++)
                o = fmaf(rec[k], W_head[k * N_APP + t], o);
            out[b * N_APP + t] = o;
        }
    }
}

extern "C" void kernel_launch(void* const* d_in, const int* in_sizes, int n_in,
                              void* d_out, int out_size)
{
    const float* x         = (const float*)d_in[0];
    const float* W_in      = (const float*)d_in[1];
    const float* b_in      = (const float*)d_in[2];
    const float* tau_param = (const float*)d_in[3];
    const float* W_rec     = (const float*)d_in[4];
    const float* g_intra   = (const float*)d_in[5];
    const float* b_intra   = (const float*)d_in[6];
    const float* g_norm    = (const float*)d_in[7];
    const float* b_norm    = (const float*)d_in[8];
    const float* W_head    = (const float*)d_in[9];
    const float* b_head    = (const float*)d_in[10];
    float* out = (float*)d_out;

    int B = in_sizes[0] / (T_STEPS * D_IN);   // 128

    cudaFuncSetAttribute(liquid_net_kernel,
                         cudaFuncAttributeMaxDynamicSharedMemorySize, SM_BYTES);

    liquid_net_kernel<<<B, 512, SM_BYTES>>>(
        x, W_in, b_in, tau_param, W_rec, g_intra, b_intra,
        g_norm, b_norm, W_head, b_head, out);
}

// round 17
// speedup vs baseline: 1.0135x; 1.0135x over previous
#include <cuda_runtime.h>
#include <math.h>

#define T_STEPS 2048
#define D_IN    16
#define H_DIM   256
#define N_APP   10
#define DT_VAL  0.1f
#define LN_EPS  1e-5f

// Shared memory layout (floats):
//  WSM [3][32][260] = 24960  W_rec rows i=128+4l+rr+1 (rr=0..2), conflict-free pad 260
//  WIN [256][20]    = 5120
//  PRM [6][256]     = 1536   (b_in, g_intra, b_intra, decay, g_norm, b_norm)
//  H   [256], REC [256], USM [2][256], XS [2][16], RED [16]
#define SM_WSM 0
#define SM_WIN (SM_WSM + 24960)
#define SM_PRM (SM_WIN + 5120)
#define SM_H   (SM_PRM + 1536)
#define SM_REC (SM_H + 256)
#define SM_USM (SM_REC + 256)
#define SM_XS  (SM_USM + 512)
#define SM_RED (SM_XS + 32)
#define SM_TOT (SM_RED + 16)
#define SM_BYTES (SM_TOT * 4)

typedef unsigned long long ull;

__device__ __forceinline__ ull fma2(ull a, ull b, ull c) {
    ull d;
    asm("fma.rn.f32x2 %0, %1, %2, %3;" : "=l"(d) : "l"(a), "l"(b), "l"(c));
    return d;
}
__device__ __forceinline__ ull dupf2(float v) {
    ull d;
    asm("mov.b64 %0, {%1, %1};" : "=l"(d) : "f"(v));
    return d;
}
__device__ __forceinline__ float lo32(ull a) { return __uint_as_float((unsigned)a); }
__device__ __forceinline__ float hi32(ull a) { return __uint_as_float((unsigned)(a >> 32)); }

extern "C" __global__ void __launch_bounds__(512, 1)
liquid_net_kernel(const float* __restrict__ x,
                  const float* __restrict__ W_in,
                  const float* __restrict__ b_in,
                  const float* __restrict__ tau_param,
                  const float* __restrict__ W_rec,
                  const float* __restrict__ g_intra,
                  const float* __restrict__ b_intra,
                  const float* __restrict__ g_norm,
                  const float* __restrict__ b_norm,
                  const float* __restrict__ W_head,
                  const float* __restrict__ b_head,
                  float* __restrict__ out)
{
    extern __shared__ float sm[];
    float* Wsm  = sm + SM_WSM;
    float* Win  = sm + SM_WIN;
    float* prm  = sm + SM_PRM;
    float* h_sh = sm + SM_H;
    float* rec  = sm + SM_REC;
    float* usm  = sm + SM_USM;
    float* xs   = sm + SM_XS;
    float* red  = sm + SM_RED;

    const int t = threadIdx.x;
    const int b = blockIdx.x;
    const int w = t >> 5;     // warp: owns j-block [16w, 16w+16)
    const int l = t & 31;     // lane: owns i in {4l..4l+3, 128+4l..128+4l+3}

    // ---------------- init ----------------
    // smem W rows: i = 128 + 4*lane + rr + 1, rr in [0,3)
    for (int idx = t; idx < 3 * 32 * 256; idx += 512) {
        int j   = idx & 255;
        int row = idx >> 8;          // 0..95
        int rr  = row >> 5;
        int ll  = row & 31;
        Wsm[row * 260 + j] = W_rec[(128 + 4 * ll + rr + 1) * 256 + j];
    }
    for (int idx = t; idx < 4096; idx += 512) {
        int jj = idx >> 4;
        int i  = idx & 15;
        Win[jj * 20 + i] = W_in[jj * 16 + i];
    }
    if (t < 256) {
        prm[t]        = b_in[t];
        prm[256 + t]  = g_intra[t];
        prm[512 + t]  = b_intra[t];
        float tau = log1pf(expf(tau_param[t]));
        prm[768 + t]  = 1.0f - DT_VAL / tau;
        prm[1024 + t] = g_norm[t];
        prm[1280 + t] = b_norm[t];
        h_sh[t] = 0.0f;
    }
    if (t < 32) {
        // xs[0] = x_0, xs[1] = x_1
        int buf = t >> 4, i = t & 15;
        xs[buf * 16 + i] = x[((size_t)b * T_STEPS + buf) * D_IN + i];
    }

    // Register W rows: i = 4l+rr (rr=0..3) and i = 128+4l. Packed over j pairs.
    ull wr0[8], wr1[8], wr2[8], wr3[8], wh0[8];
    {
        const int jb = 16 * w;
        const float2* p0 = (const float2*)(W_rec + (size_t)(4 * l + 0) * 256 + jb);
        const float2* p1 = (const float2*)(W_rec + (size_t)(4 * l + 1) * 256 + jb);
        const float2* p2 = (const float2*)(W_rec + (size_t)(4 * l + 2) * 256 + jb);
        const float2* p3 = (const float2*)(W_rec + (size_t)(4 * l + 3) * 256 + jb);
        const float2* ph = (const float2*)(W_rec + (size_t)(128 + 4 * l) * 256 + jb);
        #pragma unroll
        for (int p = 0; p < 8; p++) {
            float2 a;
            a = p0[p]; wr0[p] = (ull)__float_as_uint(a.x) | ((ull)__float_as_uint(a.y) << 32);
            a = p1[p]; wr1[p] = (ull)__float_as_uint(a.x) | ((ull)__float_as_uint(a.y) << 32);
            a = p2[p]; wr2[p] = (ull)__float_as_uint(a.x) | ((ull)__float_as_uint(a.y) << 32);
            a = p3[p]; wr3[p] = (ull)__float_as_uint(a.x) | ((ull)__float_as_uint(a.y) << 32);
            a = ph[p]; wh0[p] = (ull)__float_as_uint(a.x) | ((ull)__float_as_uint(a.y) << 32);
        }
    }
    __syncthreads();

    // prologue: warps 8-15 compute u_0 into usm[0]
    if (t >= 256) {
        int j = t - 256;
        float u = prm[j];
        const float* wi = Win + j * 20;
        #pragma unroll
        for (int i = 0; i < 16; i++) u = fmaf(xs[i], wi[i], u);
        usm[j] = u;
    }
    __syncthreads();

    const float* wsm_base = Wsm + l * 260 + 16 * w;
    const int j_ln = t & 255;   // for LN threads (t<256) this is j

    // bit-reversed lane nibble -> j offset this lane's reduced value maps to
    const int m = ((l & 1) << 3) | ((l & 2) << 1) | ((l & 4) >> 1) | ((l & 8) >> 3);

    // ---------------- recurrence ----------------
    for (int step = 0; step < T_STEPS; ++step) {
        // ---- GEMV: all 16 warps ----
        float4 hlo = *(const float4*)(h_sh + 4 * l);
        float4 hhi = *(const float4*)(h_sh + 128 + 4 * l);

        ull acc[8];
        {
            ull hp = dupf2(hlo.x);
            #pragma unroll
            for (int p = 0; p < 8; p++) acc[p] = fma2(hp, wr0[p], 0ull);
        }
        {
            ull hp = dupf2(hlo.y);
            #pragma unroll
            for (int p = 0; p < 8; p++) acc[p] = fma2(hp, wr1[p], acc[p]);
        }
        {
            ull hp = dupf2(hlo.z);
            #pragma unroll
            for (int p = 0; p < 8; p++) acc[p] = fma2(hp, wr2[p], acc[p]);
        }
        {
            ull hp = dupf2(hlo.w);
            #pragma unroll
            for (int p = 0; p < 8; p++) acc[p] = fma2(hp, wr3[p], acc[p]);
        }
        {
            ull hp = dupf2(hhi.x);
            #pragma unroll
            for (int p = 0; p < 8; p++) acc[p] = fma2(hp, wh0[p], acc[p]);
        }
        // 3 smem rows: i = 128+4l+1(+2,+3) -> hhi.y,.z,.w
        {
            float hv[3] = { hhi.y, hhi.z, hhi.w };
            #pragma unroll
            for (int rr = 0; rr < 3; rr++) {
                const ulonglong2* wp = (const ulonglong2*)(wsm_base + rr * (32 * 260));
                ull hp = dupf2(hv[rr]);
                #pragma unroll
                for (int c = 0; c < 4; c++) {
                    ulonglong2 wv = wp[c];
                    acc[2 * c]     = fma2(hp, wv.x, acc[2 * c]);
                    acc[2 * c + 1] = fma2(hp, wv.y, acc[2 * c + 1]);
                }
            }
        }

        // ---- intra-warp reduce: 16 j-values across 32 lanes ----
        float v[16];
        #pragma unroll
        for (int p = 0; p < 8; p++) { v[2 * p] = lo32(acc[p]); v[2 * p + 1] = hi32(acc[p]); }
        {   // off=1, keep-half = 8
            bool up = (l & 1);
            #pragma unroll
            for (int k = 0; k < 8; k++) {
                float send = up ? v[k] : v[8 + k];
                float keep = up ? v[8 + k] : v[k];
                v[k] = keep + __shfl_xor_sync(0xffffffffu, send, 1);
            }
        }
        {   // off=2, half=4
            bool up = (l & 2);
            #pragma unroll
            for (int k = 0; k < 4; k++) {
                float send = up ? v[k] : v[4 + k];
                float keep = up ? v[4 + k] : v[k];
                v[k] = keep + __shfl_xor_sync(0xffffffffu, send, 2);
            }
        }
        {   // off=4, half=2
            bool up = (l & 4);
            #pragma unroll
            for (int k = 0; k < 2; k++) {
                float send = up ? v[k] : v[2 + k];
                float keep = up ? v[2 + k] : v[k];
                v[k] = keep + __shfl_xor_sync(0xffffffffu, send, 4);
            }
        }
        {   // off=8, half=1
            bool up = (l & 8);
            float send = up ? v[0] : v[1];
            float keep = up ? v[1] : v[0];
            v[0] = keep + __shfl_xor_sync(0xffffffffu, send, 8);
        }
        v[0] += __shfl_xor_sync(0xffffffffu, v[0], 16);
        if (l < 16) rec[16 * w + m] = v[0];

        __syncthreads();

        if (t < 256) {
            // ---- LN + state update (warps 0-7) ----
            float pre = rec[j_ln] + usm[(step & 1) * 256 + j_ln];

            float s  = pre;
            float s2 = pre * pre;
            #pragma unroll
            for (int off = 16; off > 0; off >>= 1) {
                s  += __shfl_xor_sync(0xffffffffu, s,  off);
                s2 += __shfl_xor_sync(0xffffffffu, s2, off);
            }
            if (l == 0) { red[w] = s; red[8 + w] = s2; }
            asm volatile("bar.sync 1, 256;" ::: "memory");
            float sum = 0.0f, sum2 = 0.0f;
            #pragma unroll
            for (int k = 0; k < 8; k++) { sum += red[k]; sum2 += red[8 + k]; }
            float mu   = sum * (1.0f / H_DIM);
            float var  = fmaf(-mu, mu, sum2 * (1.0f / H_DIM));
            float rstd = rsqrtf(var + LN_EPS);

            float f = tanhf(fmaf((pre - mu) * rstd, prm[256 + j_ln], prm[512 + j_ln]));
            float hn = fmaf(h_sh[j_ln], prm[768 + j_ln], DT_VAL * f);
            hn = fminf(10.0f, fmaxf(-10.0f, hn));
            h_sh[j_ln] = hn;
        } else {
            // ---- warps 8-15: next-step input projection + x prefetch ----
            int j = t - 256;
            int ns = step + 1;
            const float* xq = xs + (ns & 1) * 16;
            float u = prm[j];
            const float* wi = Win + j * 20;
            #pragma unroll
            for (int i = 0; i < 16; i++) u = fmaf(xq[i], wi[i], u);
            usm[(ns & 1) * 256 + j] = u;

            if (j < 16) {
                int ps = step + 2;
                int cl = ps < T_STEPS ? ps : (T_STEPS - 1);
                float xv = x[((size_t)b * T_STEPS + cl) * D_IN + j];
                xs[(ps & 1) * 16 + j] = xv;
            }
        }
        __syncthreads();
    }

    // ---------------- final LN + head ----------------
    if (t < 256) {
        float hv = h_sh[j_ln];
        float s  = hv;
        float s2 = hv * hv;
        #pragma unroll
        for (int off = 16; off > 0; off >>= 1) {
            s  += __shfl_xor_sync(0xffffffffu, s,  off);
            s2 += __shfl_xor_sync(0xffffffffu, s2, off);
        }
        int w8 = t >> 5;
        if ((t & 31) == 0) { red[w8] = s; red[8 + w8] = s2; }
        asm volatile("bar.sync 1, 256;" ::: "memory");
        float sum = 0.0f, sum2 = 0.0f;
        #pragma unroll
        for (int k = 0; k < 8; k++) { sum += red[k]; sum2 += red[8 + k]; }
        float mu   = sum * (1.0f / H_DIM);
        float var  = fmaf(-mu, mu, sum2 * (1.0f / H_DIM));
        float rstd = rsqrtf(var + LN_EPS);
        float hn = fmaf((hv - mu) * rstd, prm[1024 + j_ln], prm[1280 + j_ln]);
        rec[j_ln] = hn;
        asm volatile("bar.sync 1, 256;" ::: "memory");

        if (t < N_APP) {
            float o = b_head[t];
            #pragma unroll 8
            for (int k = 0; k < H_DIM; k++)
                o = fmaf(rec[k], W_head[k * N_APP + t], o);
            out[b * N_APP + t] = o;
        }
    }
}

extern "C" void kernel_launch(void* const* d_in, const int* in_sizes, int n_in,
                              void* d_out, int out_size)
{
    const float* x         = (const float*)d_in[0];
    const float* W_in      = (const float*)d_in[1];
    const float* b_in      = (const float*)d_in[2];
    const float* tau_param = (const float*)d_in[3];
    const float* W_rec     = (const float*)d_in[4];
    const float* g_intra   = (const float*)d_in[5];
    const float* b_intra   = (const float*)d_in[6];
    const float* g_norm    = (const float*)d_in[7];
    const float* b_norm    = (const float*)d_in[8];
    const float* W_head    = (const float*)d_in[9];
    const float* b_head    = (const float*)d_in[10];
    float* out = (float*)d_out;

    int B = in_sizes[0] / (T_STEPS * D_IN);   // 128

    cudaFuncSetAttribute(liquid_net_kernel,
                         cudaFuncAttributeMaxDynamicSharedMemorySize, SM_BYTES);

    liquid_net_kernel<<<B, 512, SM_BYTES>>>(
        x, W_in, b_in, tau_param, W_rec, g_intra, b_intra,
        g_norm, b_norm, W_head, b_head, out);
}